// round 17
// baseline (speedup 1.0000x reference)
#include <cuda_runtime.h>
#include <cuda_bf16.h>

// Problem constants (fixed by setup_inputs):
// x_0  : [128, 64, 16] f32   (d_in[0])
// x_h  : [128, 64, 16] f32   (d_in[1], UNUSED — reference bug recomputes from x_0)
// Vm   : [64, 1, 64, 16] f32 (d_in[2])
// Vh   : [64, 1, 16, 64] f32 (d_in[3])
// out  : [128, 64, 16] f32
//
// out[b,k,d] = sum_v P[n,kv]*Q[n,kv], n = b*16+d, kv = k*16+v
//   P = Xa[2048x64] * Wm^T,  Q = Xb[2048x64] * Wh^T
// bf16 3-term split folded into K=192: X=[hi|lo|hi], W=[whi|whi|wlo]
// -> X*W = hi*whi + lo*whi + hi*wlo (residual ~2^-18).
//
// R17: fused single kernel at 512 threads (16 warps = 4/SMSP).
// Staging: in-CTA f32->composite-bf16 conversion (12 LDG.128/thread).
// Mainloop: warp tile 32n x 32kv, ldmatrix.x4 + interleaved A/B HMMA.
// Epilogue: in-register dot over v + shfl reduce.

#define XROWB 400        // padded smem row stride in bytes (192 bf16 + 16B pad)
#define SMEM_MAIN 204800 // 4 regions x 128 rows x 400 B
#define NTHR 512
#define RSZ 51200u

__device__ __forceinline__ void ldsm_x4(unsigned& r0, unsigned& r1,
                                        unsigned& r2, unsigned& r3,
                                        unsigned addr) {
    asm volatile("ldmatrix.sync.aligned.m8n8.x4.shared.b16 {%0,%1,%2,%3}, [%4];"
        : "=r"(r0), "=r"(r1), "=r"(r2), "=r"(r3) : "r"(addr));
}
__device__ __forceinline__ void mma_bf16(float c[4],
        unsigned a0, unsigned a1, unsigned a2, unsigned a3,
        unsigned b0, unsigned b1) {
    asm volatile(
        "mma.sync.aligned.m16n8k16.row.col.f32.bf16.bf16.f32 "
        "{%0,%1,%2,%3},{%4,%5,%6,%7},{%8,%9},{%0,%1,%2,%3};"
        : "+f"(c[0]), "+f"(c[1]), "+f"(c[2]), "+f"(c[3])
        : "r"(a0), "r"(a1), "r"(a2), "r"(a3), "r"(b0), "r"(b1));
}
__device__ __forceinline__ void sts16(unsigned addr, unsigned short v) {
    asm volatile("st.shared.u16 [%0], %1;" :: "r"(addr), "h"(v));
}
__device__ __forceinline__ void sts32(unsigned addr, unsigned v) {
    asm volatile("st.shared.u32 [%0], %1;" :: "r"(addr), "r"(v));
}
__device__ __forceinline__ unsigned short bhi(float v) {
    return __bfloat16_as_ushort(__float2bfloat16(v));
}
__device__ __forceinline__ unsigned short blo(float v, unsigned short h) {
    float hf = __bfloat162float(__ushort_as_bfloat16(h));
    return __bfloat16_as_ushort(__float2bfloat16(v - hf));
}

__global__ void __launch_bounds__(NTHR, 1)
cin_fused_kernel(const float* __restrict__ x0,
                 const float* __restrict__ Vm,
                 const float* __restrict__ Vh,
                 float* __restrict__ out)
{
    extern __shared__ __align__(16) unsigned char smem[];
    const unsigned sXa = (unsigned)__cvta_generic_to_shared(smem);
    const unsigned sXb = sXa + RSZ;
    const unsigned sWm = sXa + 2u * RSZ;
    const unsigned sWh = sXa + 3u * RSZ;

    const int tid   = threadIdx.x;
    const int k0    = blockIdx.x * 8;     // 8 k per CTA (128 kv cols)
    const int ntile = blockIdx.y * 128;   // 128 n rows
    const int b0    = ntile >> 4;         // 8 b per CTA

    // ================= staging: load f32, convert, store composite =========
    // 512 threads: thread handles float4 index (tid&255) of tiles
    // {(tid>>8)*4 + t, t=0..3} for each of X / Vm / Vh.
    {
        const int e   = tid & 255;         // float4 index within a tile
        const int tg  = (tid >> 8) * 4;    // tile group base (0 or 4)

        float4 xw[4], vmw[4], vhw[4];
        const float4* x4  = reinterpret_cast<const float4*>(x0);
        const float4* vm4 = reinterpret_cast<const float4*>(Vm);
        const float4* vh4 = reinterpret_cast<const float4*>(Vh);
        #pragma unroll
        for (int t = 0; t < 4; t++) {
            xw[t]  = x4[(b0 + tg + t) * 256 + e];
            vmw[t] = vm4[(k0 + tg + t) * 256 + e];
            vhw[t] = vh4[(k0 + tg + t) * 256 + e];
        }

        const int m0   = e * 4;            // flat element base within a tile
        const int i0   = m0 >> 4;          // for [i,16]-major views (Xa/Wm)
        const int d0   = m0 & 15;
        const int rowf = m0 >> 6;          // for flat [*,64] views (Xb/Wh)
        const int j0   = m0 & 63;

        #pragma unroll
        for (int t = 0; t < 4; t++) {
            const int tt = tg + t;         // tile 0..7
            // ---- X tile b0+tt ----
            {
                float vals[4] = {xw[t].x, xw[t].y, xw[t].z, xw[t].w};
                unsigned short hi[4], lo[4];
                #pragma unroll
                for (int u = 0; u < 4; u++) {
                    hi[u] = bhi(vals[u]);
                    lo[u] = blo(vals[u], hi[u]);
                }
                // Xa[n = tt*16 + d][col i], segs [hi|lo|hi]
                #pragma unroll
                for (int u = 0; u < 4; u++) {
                    unsigned base = sXa + (unsigned)((tt * 16 + d0 + u) * XROWB + i0 * 2);
                    sts16(base,        hi[u]);
                    sts16(base + 128u, lo[u]);
                    sts16(base + 256u, hi[u]);
                }
                // Xb[n = tt*16 + rowf][col j0..j0+3], packed
                unsigned hA = (unsigned)hi[0] | ((unsigned)hi[1] << 16);
                unsigned hB = (unsigned)hi[2] | ((unsigned)hi[3] << 16);
                unsigned lA = (unsigned)lo[0] | ((unsigned)lo[1] << 16);
                unsigned lB = (unsigned)lo[2] | ((unsigned)lo[3] << 16);
                unsigned base = sXb + (unsigned)((tt * 16 + rowf) * XROWB + j0 * 2);
                sts32(base,        hA); sts32(base + 4u,   hB);
                sts32(base + 128u, lA); sts32(base + 132u, lB);
                sts32(base + 256u, hA); sts32(base + 260u, hB);
            }
            // ---- Wm tile k0+tt: segs [hi|hi|lo] ----
            {
                float vals[4] = {vmw[t].x, vmw[t].y, vmw[t].z, vmw[t].w};
                #pragma unroll
                for (int u = 0; u < 4; u++) {
                    unsigned short hi = bhi(vals[u]);
                    unsigned short lo = blo(vals[u], hi);
                    unsigned base = sWm + (unsigned)((tt * 16 + d0 + u) * XROWB + i0 * 2);
                    sts16(base,        hi);
                    sts16(base + 128u, hi);
                    sts16(base + 256u, lo);
                }
            }
            // ---- Wh tile k0+tt: segs [hi|hi|lo], packed ----
            {
                float vals[4] = {vhw[t].x, vhw[t].y, vhw[t].z, vhw[t].w};
                unsigned short hi[4], lo[4];
                #pragma unroll
                for (int u = 0; u < 4; u++) {
                    hi[u] = bhi(vals[u]);
                    lo[u] = blo(vals[u], hi[u]);
                }
                unsigned hA = (unsigned)hi[0] | ((unsigned)hi[1] << 16);
                unsigned hB = (unsigned)hi[2] | ((unsigned)hi[3] << 16);
                unsigned lA = (unsigned)lo[0] | ((unsigned)lo[1] << 16);
                unsigned lB = (unsigned)lo[2] | ((unsigned)lo[3] << 16);
                unsigned base = sWh + (unsigned)((tt * 16 + rowf) * XROWB + j0 * 2);
                sts32(base,        hA); sts32(base + 4u,   hB);
                sts32(base + 128u, hA); sts32(base + 132u, hB);
                sts32(base + 256u, lA); sts32(base + 260u, lB);
            }
        }
    }
    __syncthreads();

    // ================= mainloop (R14 core: 16 warps, 32n x 32kv) ============
    // warp w: nw = w&3 (rows nw*32), kw = w>>2 (cols kw*32)
    const int w    = tid >> 5;
    const int lane = tid & 31;
    const int nw   = w & 3;
    const int kw   = w >> 2;
    const int g    = lane >> 2;
    const int q    = lane & 3;
    const int m    = lane >> 3;

    unsigned aA[2], aB[2];
    #pragma unroll
    for (int mi = 0; mi < 2; mi++) {
        unsigned off = (unsigned)((nw * 32 + mi * 16 + (lane & 15)) * XROWB
                                  + (lane >> 4) * 16);
        aA[mi] = sXa + off;
        aB[mi] = sXb + off;
    }
    unsigned bA[2], bB[2];
    #pragma unroll
    for (int bi = 0; bi < 2; bi++) {
        unsigned off = (unsigned)((kw * 32 + bi * 16 + (m >> 1) * 8 + (lane & 7)) * XROWB
                                  + (m & 1) * 16);
        bA[bi] = sWm + off;
        bB[bi] = sWh + off;
    }

    float cf[2][4][4], cq[2][4][4];
    #pragma unroll
    for (int mi = 0; mi < 2; mi++)
        #pragma unroll
        for (int nj = 0; nj < 4; nj++)
            #pragma unroll
            for (int p = 0; p < 4; p++) { cf[mi][nj][p] = 0.f; cq[mi][nj][p] = 0.f; }

    #pragma unroll
    for (int ks = 0; ks < 12; ks++) {
        const unsigned off = (unsigned)(ks * 32);
        unsigned xa0[2], xa1[2], xa2[2], xa3[2];
        unsigned xb0[2], xb1[2], xb2[2], xb3[2];
        #pragma unroll
        for (int mi = 0; mi < 2; mi++) {
            ldsm_x4(xa0[mi], xa1[mi], xa2[mi], xa3[mi], aA[mi] + off);
            ldsm_x4(xb0[mi], xb1[mi], xb2[mi], xb3[mi], aB[mi] + off);
        }
        #pragma unroll
        for (int bi = 0; bi < 2; bi++) {
            unsigned wa0, wa1, wa2, wa3, wb0, wb1, wb2, wb3;
            ldsm_x4(wa0, wa1, wa2, wa3, bA[bi] + off);
            ldsm_x4(wb0, wb1, wb2, wb3, bB[bi] + off);
            #pragma unroll
            for (int mi = 0; mi < 2; mi++) {
                mma_bf16(cf[mi][2 * bi],     xa0[mi], xa1[mi], xa2[mi], xa3[mi], wa0, wa1);
                mma_bf16(cf[mi][2 * bi + 1], xa0[mi], xa1[mi], xa2[mi], xa3[mi], wa2, wa3);
                mma_bf16(cq[mi][2 * bi],     xb0[mi], xb1[mi], xb2[mi], xb3[mi], wb0, wb1);
                mma_bf16(cq[mi][2 * bi + 1], xb0[mi], xb1[mi], xb2[mi], xb3[mi], wb2, wb3);
            }
        }
    }

    // ================= epilogue: in-register dot over v =====================
    // col of frag nj elem 0/1 = kw*32 + nj*8 + 2q (+1) -> k_local = kw*2 + (nj>>1)
    float sl[2][2], sh[2][2];
    #pragma unroll
    for (int mi = 0; mi < 2; mi++)
        #pragma unroll
        for (int kx = 0; kx < 2; kx++) { sl[mi][kx] = 0.f; sh[mi][kx] = 0.f; }
    #pragma unroll
    for (int mi = 0; mi < 2; mi++)
        #pragma unroll
        for (int nj = 0; nj < 4; nj++) {
            int kx = nj >> 1;
            sl[mi][kx] = fmaf(cf[mi][nj][0], cq[mi][nj][0],
                         fmaf(cf[mi][nj][1], cq[mi][nj][1], sl[mi][kx]));
            sh[mi][kx] = fmaf(cf[mi][nj][2], cq[mi][nj][2],
                         fmaf(cf[mi][nj][3], cq[mi][nj][3], sh[mi][kx]));
        }
    #pragma unroll
    for (int mi = 0; mi < 2; mi++)
        #pragma unroll
        for (int kx = 0; kx < 2; kx++) {
            sl[mi][kx] += __shfl_xor_sync(0xffffffffu, sl[mi][kx], 1);
            sl[mi][kx] += __shfl_xor_sync(0xffffffffu, sl[mi][kx], 2);
            sh[mi][kx] += __shfl_xor_sync(0xffffffffu, sh[mi][kx], 1);
            sh[mi][kx] += __shfl_xor_sync(0xffffffffu, sh[mi][kx], 2);
        }
    if (q == 0) {
        #pragma unroll
        for (int mi = 0; mi < 2; mi++) {
            int n0 = ntile + nw * 32 + mi * 16 + g;
            int n1 = n0 + 8;
            #pragma unroll
            for (int kx = 0; kx < 2; kx++) {
                int k = k0 + kw * 2 + kx;
                out[(n0 >> 4) * 1024 + k * 16 + (n0 & 15)] = sl[mi][kx];
                out[(n1 >> 4) * 1024 + k * 16 + (n1 & 15)] = sh[mi][kx];
            }
        }
    }
}

extern "C" void kernel_launch(void* const* d_in, const int* in_sizes, int n_in,
                              void* d_out, int out_size) {
    (void)in_sizes; (void)n_in; (void)out_size;
    const float* x0 = (const float*)d_in[0];
    // d_in[1] (x_h) intentionally unused: reference recomputes it from x_0.
    const float* Vm = (const float*)d_in[2];
    const float* Vh = (const float*)d_in[3];
    float* out = (float*)d_out;

    cudaFuncSetAttribute(cin_fused_kernel,
                         cudaFuncAttributeMaxDynamicSharedMemorySize, SMEM_MAIN);

    dim3 grid(8, 16);    // (kv-tiles of 128 cols, n-tiles of 128 rows) = 128 CTAs
    cin_fused_kernel<<<grid, NTHR, SMEM_MAIN>>>(x0, Vm, Vh, out);
}